// round 7
// baseline (speedup 1.0000x reference)
#include <cuda_runtime.h>
#include <math.h>

// Problem constants (fixed by the dataset)
#define NN   50000
#define EE   400000
#define ETOT (EE + NN)          // edges + self loops
#define HID  64
#define HEADS 4
#define C1   (HEADS * HID)      // 256

// ---------------- scratch (no allocation allowed -> __device__ globals) -------------
__device__ int g_is64;                            // edge_index dtype flag
__device__ int g_src[ETOT];                       // decoded int32 edge endpoints
__device__ int g_dst[ETOT];

__device__ __align__(16) float g_h1[NN * C1];     // layer1 features per head  [N,4,64]
__device__ __align__(16) float g_out1[NN * HID];  // layer1 head-mean accumulator [N,64]
__device__ __align__(16) float g_as1[NN * HEADS]; // a_src [N,4]
__device__ __align__(16) float g_ad1[NN * HEADS]; // a_dst [N,4]
__device__ __align__(16) float g_dn1[NN * HEADS]; // denom -> 0.25/denom after k_rcp1
__device__ __align__(16) float g_ex1[ETOT * HEADS]; // per-edge exp values

__device__ __align__(16) float g_h2[NN * HID];    // layer2 features
__device__ float g_as2[NN];
__device__ float g_ad2[NN];
__device__ float g_dn2[NN];                       // denom -> 1/denom after k_rcp2
__device__ float g_ex2[ETOT];
__device__ __align__(16) float g_out2[NN * HID];

// ---------------- helpers ----------------
__device__ __forceinline__ float lrelu(float x) { return x > 0.f ? x : 0.2f * x; }
__device__ __forceinline__ float elu_f(float x) { return x > 0.f ? x : expm1f(x); }
__device__ __forceinline__ int clampN(int v) { return v < 0 ? 0 : (v >= NN ? NN - 1 : v); }

// ---------------- kernels ----------------

// Detect whether edge_index is int64 or int32 (reads 128B only; safe for both).
__global__ void k_detect(const void* ei) {
    const long long* p = (const long long*)ei;
    int ok = 1;
    for (int i = 0; i < 16; i++) {
        long long v = p[i];
        if (v < 0 || v >= NN) ok = 0;
    }
    g_is64 = ok;
}

// Decode edge index (either dtype -> int32, self loops appended) + zero
// accumulators. Indices clamped into [0, NN): decode mismatch surfaces as
// rel_err, never as an illegal access.
__global__ void k_prep(const void* ei) {
    int i = blockIdx.x * blockDim.x + threadIdx.x;
    int stride = gridDim.x * blockDim.x;
    if (g_is64) {
        const long long* p = (const long long*)ei;
        for (int j = i; j < ETOT; j += stride) {
            if (j < EE) { g_src[j] = clampN((int)p[j]); g_dst[j] = clampN((int)p[EE + j]); }
            else        { g_src[j] = g_dst[j] = j - EE; }
        }
    } else {
        const int* p = (const int*)ei;
        for (int j = i; j < ETOT; j += stride) {
            if (j < EE) { g_src[j] = clampN(p[j]); g_dst[j] = clampN(p[EE + j]); }
            else        { g_src[j] = g_dst[j] = j - EE; }
        }
    }
    for (int j = i; j < NN * HID; j += stride) { g_out1[j] = 0.f; g_out2[j] = 0.f; }
    for (int j = i; j < NN * HEADS; j += stride) g_dn1[j] = 0.f;
    for (int j = i; j < NN; j += stride)         g_dn2[j] = 0.f;
}

// h1 = x @ W1 (16 -> 256) + per-head attention dots. 8 nodes/block, W1 reused.
#define NB1 8
__global__ void k_gemm1(const float* __restrict__ x, const float* __restrict__ W,
                        const float* __restrict__ asw, const float* __restrict__ adw) {
    int t = threadIdx.x;                // channel 0..255
    int nb = blockIdx.x * NB1;
    __shared__ float xs[NB1][16];
    __shared__ float ss[8][NB1], sd[8][NB1];   // [warp][node]
    if (t < NB1 * 16) {
        int n = nb + (t >> 4);
        xs[t >> 4][t & 15] = (n < NN) ? x[n * 16 + (t & 15)] : 0.f;
    }
    __syncthreads();
    float acc[NB1];
#pragma unroll
    for (int j = 0; j < NB1; j++) acc[j] = 0.f;
#pragma unroll
    for (int k = 0; k < 16; k++) {
        float wv = W[k * C1 + t];
#pragma unroll
        for (int j = 0; j < NB1; j++) acc[j] = fmaf(xs[j][k], wv, acc[j]);
    }
#pragma unroll
    for (int j = 0; j < NB1; j++) {
        int n = nb + j;
        if (n < NN) g_h1[n * C1 + t] = acc[j];
    }
    float aw = asw[t], dw = adw[t];
    int w = t >> 5, lane = t & 31;
#pragma unroll
    for (int j = 0; j < NB1; j++) {
        float ps = acc[j] * aw;
        float pd = acc[j] * dw;
#pragma unroll
        for (int o = 16; o > 0; o >>= 1) {
            ps += __shfl_down_sync(0xffffffffu, ps, o);
            pd += __shfl_down_sync(0xffffffffu, pd, o);
        }
        if (lane == 0) { ss[w][j] = ps; sd[w][j] = pd; }
    }
    __syncthreads();
    if (t < NB1 * HEADS) {              // node j = t>>2, head h = t&3
        int j = t >> 2, h = t & 3;
        int n = nb + j;
        if (n < NN) {
            g_as1[n * HEADS + h] = ss[2 * h][j] + ss[2 * h + 1][j];
            g_ad1[n * HEADS + h] = sd[2 * h][j] + sd[2 * h + 1][j];
        }
    }
}

// exp(leaky_relu(e)) per edge (logits O(1): no max shift), store, vector-RED denom.
__global__ void k_exp1() {
    int idx = blockIdx.x * blockDim.x + threadIdx.x;
    if (idx >= ETOT) return;
    int s = g_src[idx], d = g_dst[idx];
    float4 a = *(const float4*)&g_as1[s * 4];
    float4 b = *(const float4*)&g_ad1[d * 4];
    float4 e;
    e.x = expf(lrelu(a.x + b.x));
    e.y = expf(lrelu(a.y + b.y));
    e.z = expf(lrelu(a.z + b.z));
    e.w = expf(lrelu(a.w + b.w));
    *(float4*)&g_ex1[idx * 4] = e;
    atomicAdd((float4*)&g_dn1[d * 4], e);
}

// Per-node reciprocal folds (division hoisted out of the per-edge scatters).
__global__ void k_rcp1() {
    int i = blockIdx.x * blockDim.x + threadIdx.x;
    if (i < NN * HEADS) g_dn1[i] = 0.25f / (g_dn1[i] + 1e-16f);
}
__global__ void k_rcp2() {
    int i = blockIdx.x * blockDim.x + threadIdx.x;
    if (i < NN) g_dn2[i] = 1.0f / (g_dn2[i] + 1e-16f);
}

// message scatter (layer 1): one warp per edge, head-mean fused, no divides.
__global__ void k_scat1() {
    int gt = blockIdx.x * blockDim.x + threadIdx.x;
    int e = gt >> 5, lane = gt & 31;
    if (e >= ETOT) return;
    int s = g_src[e], d = g_dst[e];
    float4 ex = *(const float4*)&g_ex1[e * 4];     // same addr in warp -> broadcast
    float4 rc = *(const float4*)&g_dn1[d * 4];     // already 0.25/denom
    float a0 = ex.x * rc.x;
    float a1 = ex.y * rc.y;
    float a2 = ex.z * rc.z;
    float a3 = ex.w * rc.w;
    const float2* hp = (const float2*)&g_h1[s * C1];   // [4][32] float2
    float2 v0 = hp[lane];
    float2 v1 = hp[32 + lane];
    float2 v2 = hp[64 + lane];
    float2 v3 = hp[96 + lane];
    float2 v;
    v.x = a0 * v0.x + a1 * v1.x + a2 * v2.x + a3 * v3.x;
    v.y = a0 * v0.y + a1 * v1.y + a2 * v2.y + a3 * v3.y;
    atomicAdd((float2*)&g_out1[d * HID] + lane, v);
}

// h2 = elu(out1 + b1) @ W2 (64 -> 64) + attention dots. 16 nodes/block.
#define NB2 16
__global__ void k_gemm2(const float* __restrict__ W, const float* __restrict__ b1,
                        const float* __restrict__ asw, const float* __restrict__ adw) {
    int t = threadIdx.x;
    int sub = t >> 6, tc = t & 63;      // 4 subs x 64 channels
    int nb = blockIdx.x * NB2;
    __shared__ float xs[NB2][65];       // padded
    __shared__ float ss[8][4], sd[8][4]; // [warp][node-within-sub]
    for (int j = t; j < NB2 * 64; j += 256) {
        int n = nb + (j >> 6);
        xs[j >> 6][j & 63] = (n < NN) ? elu_f(g_out1[n * 64 + (j & 63)] + b1[j & 63]) : 0.f;
    }
    __syncthreads();
    float acc[4] = {0.f, 0.f, 0.f, 0.f};
#pragma unroll 8
    for (int k = 0; k < 64; k++) {
        float wv = W[k * 64 + tc];
#pragma unroll
        for (int j = 0; j < 4; j++) acc[j] = fmaf(xs[sub * 4 + j][k], wv, acc[j]);
    }
    float aw = asw[tc], dw = adw[tc];
    int w = t >> 5, lane = t & 31;
#pragma unroll
    for (int j = 0; j < 4; j++) {
        int n = nb + sub * 4 + j;
        if (n < NN) g_h2[n * 64 + tc] = acc[j];
        float ps = acc[j] * aw;
        float pd = acc[j] * dw;
#pragma unroll
        for (int o = 16; o > 0; o >>= 1) {
            ps += __shfl_down_sync(0xffffffffu, ps, o);
            pd += __shfl_down_sync(0xffffffffu, pd, o);
        }
        if (lane == 0) { ss[w][j] = ps; sd[w][j] = pd; }
    }
    __syncthreads();
    if (t < NB2) {
        int n = nb + t;
        if (n < NN) {
            int wbase = 2 * (t >> 2);    // two warps per sub
            g_as2[n] = ss[wbase][t & 3] + ss[wbase + 1][t & 3];
            g_ad2[n] = sd[wbase][t & 3] + sd[wbase + 1][t & 3];
        }
    }
}

__global__ void k_exp2() {
    int idx = blockIdx.x * blockDim.x + threadIdx.x;
    if (idx >= ETOT) return;
    int s = g_src[idx], d = g_dst[idx];
    float ex = expf(lrelu(g_as2[s] + g_ad2[d]));
    g_ex2[idx] = ex;
    atomicAdd(&g_dn2[d], ex);
}

// message scatter (layer 2): one warp per edge, float2 per lane, no divides.
__global__ void k_scat2() {
    int gt = blockIdx.x * blockDim.x + threadIdx.x;
    int e = gt >> 5, lane = gt & 31;
    if (e >= ETOT) return;
    int s = g_src[e], d = g_dst[e];
    float alpha = g_ex2[e] * g_dn2[d];             // dn2 already reciprocal
    float2 h = ((const float2*)&g_h2[s * 64])[lane];
    float2 v; v.x = alpha * h.x; v.y = alpha * h.y;
    atomicAdd((float2*)&g_out2[d * 64] + lane, v);
}

__global__ void k_fin2(const float* __restrict__ b2, float* __restrict__ out) {
    int i = blockIdx.x * blockDim.x + threadIdx.x;
    if (i >= NN * HID) return;
    out[i] = elu_f(g_out2[i] + b2[i & 63]);
}

// ---------------- launch ----------------
extern "C" void kernel_launch(void* const* d_in, const int* in_sizes, int n_in,
                              void* d_out, int out_size) {
    const float* x    = (const float*)d_in[0];
    const void*  ei   = d_in[1];               // int32 or int64, detected on device
    const float* W1   = (const float*)d_in[2];
    const float* as1w = (const float*)d_in[3];
    const float* ad1w = (const float*)d_in[4];
    const float* b1   = (const float*)d_in[5];
    const float* W2   = (const float*)d_in[6];
    const float* as2w = (const float*)d_in[7];
    const float* ad2w = (const float*)d_in[8];
    const float* b2   = (const float*)d_in[9];
    float*       out  = (float*)d_out;

    const int TB = 256;
    int edge_blocks = (ETOT + TB - 1) / TB;                 // thread per edge
    int warp_blocks = (ETOT * 32 + TB - 1) / TB;            // warp per edge
    int node_blocks = (NN * HID + TB - 1) / TB;

    k_detect<<<1, 1>>>(ei);
    k_prep<<<2048, TB>>>(ei);
    k_gemm1<<<(NN + NB1 - 1) / NB1, TB>>>(x, W1, as1w, ad1w);
    k_exp1<<<edge_blocks, TB>>>();
    k_rcp1<<<(NN * HEADS + TB - 1) / TB, TB>>>();
    k_scat1<<<warp_blocks, TB>>>();
    k_gemm2<<<(NN + NB2 - 1) / NB2, TB>>>(W2, b1, as2w, ad2w);
    k_exp2<<<edge_blocks, TB>>>();
    k_rcp2<<<(NN + TB - 1) / TB, TB>>>();
    k_scat2<<<warp_blocks, TB>>>();
    k_fin2<<<node_blocks, TB>>>(b2, out);
}

// round 9
// speedup vs baseline: 1.2169x; 1.2169x over previous
#include <cuda_runtime.h>
#include <math.h>

// Problem constants (fixed by the dataset)
#define NN   50000
#define EE   400000
#define ETOT (EE + NN)          // edges + self loops
#define HID  64
#define HEADS 4
#define C1   (HEADS * HID)      // 256

// ---------------- scratch (no allocation allowed -> __device__ globals) -------------
__device__ int g_src[ETOT];                       // decoded int32 edge endpoints
__device__ int g_dst[ETOT];

__device__ __align__(16) float g_h1[NN * C1];     // layer1 features per head  [N,4,64]
__device__ __align__(16) float g_out1[NN * HID];  // layer1 head-mean accumulator [N,64]
__device__ __align__(16) float g_as1[NN * HEADS]; // a_src [N,4]
__device__ __align__(16) float g_ad1[NN * HEADS]; // a_dst [N,4]
__device__ __align__(16) float g_dn1[NN * HEADS]; // denom -> 0.25/denom after k_rcp1
__device__ __align__(16) float g_ex1[ETOT * HEADS]; // per-edge exp values

__device__ __align__(16) float g_h2[NN * HID];    // layer2 features
__device__ float g_as2[NN];
__device__ float g_ad2[NN];
__device__ float g_dn2[NN];                       // denom -> 1/denom after k_rcp2
__device__ float g_ex2[ETOT];
__device__ __align__(16) float g_out2[NN * HID];

// ---------------- helpers ----------------
__device__ __forceinline__ float lrelu(float x) { return x > 0.f ? x : 0.2f * x; }
__device__ __forceinline__ float elu_f(float x) { return x > 0.f ? x : expm1f(x); }
__device__ __forceinline__ int clampN(int v) { return v < 0 ? 0 : (v >= NN ? NN - 1 : v); }

// ---------------- kernels ----------------

// Decode edge index (either dtype -> int32, self loops appended) + zero
// accumulators. Dtype detection is done locally per thread from the first
// 16 values (128B, L2-hot) — no separate serialized detect launch.
// Indices clamped into [0, NN): mismatch surfaces as rel_err, never as IMA.
__global__ void k_prep(const void* ei) {
    const long long* p64 = (const long long*)ei;
    int is64 = 1;
#pragma unroll
    for (int k = 0; k < 16; k++) {
        long long v = p64[k];
        if (v < 0 || v >= NN) is64 = 0;
    }
    int i = blockIdx.x * blockDim.x + threadIdx.x;
    int stride = gridDim.x * blockDim.x;
    if (is64) {
        for (int j = i; j < ETOT; j += stride) {
            if (j < EE) { g_src[j] = clampN((int)p64[j]); g_dst[j] = clampN((int)p64[EE + j]); }
            else        { g_src[j] = g_dst[j] = j - EE; }
        }
    } else {
        const int* p = (const int*)ei;
        for (int j = i; j < ETOT; j += stride) {
            if (j < EE) { g_src[j] = clampN(p[j]); g_dst[j] = clampN(p[EE + j]); }
            else        { g_src[j] = g_dst[j] = j - EE; }
        }
    }
    for (int j = i; j < NN * HID; j += stride) { g_out1[j] = 0.f; g_out2[j] = 0.f; }
    for (int j = i; j < NN * HEADS; j += stride) g_dn1[j] = 0.f;
    for (int j = i; j < NN; j += stride)         g_dn2[j] = 0.f;
}

// h1 = x @ W1 (16 -> 256) + per-head attention dots. 8 nodes/block, W1 reused.
#define NB1 8
__global__ void k_gemm1(const float* __restrict__ x, const float* __restrict__ W,
                        const float* __restrict__ asw, const float* __restrict__ adw) {
    int t = threadIdx.x;                // channel 0..255
    int nb = blockIdx.x * NB1;
    __shared__ float xs[NB1][16];
    __shared__ float ss[8][NB1], sd[8][NB1];   // [warp][node]
    if (t < NB1 * 16) {
        int n = nb + (t >> 4);
        xs[t >> 4][t & 15] = (n < NN) ? x[n * 16 + (t & 15)] : 0.f;
    }
    __syncthreads();
    float acc[NB1];
#pragma unroll
    for (int j = 0; j < NB1; j++) acc[j] = 0.f;
#pragma unroll
    for (int k = 0; k < 16; k++) {
        float wv = W[k * C1 + t];
#pragma unroll
        for (int j = 0; j < NB1; j++) acc[j] = fmaf(xs[j][k], wv, acc[j]);
    }
#pragma unroll
    for (int j = 0; j < NB1; j++) {
        int n = nb + j;
        if (n < NN) g_h1[n * C1 + t] = acc[j];
    }
    float aw = asw[t], dw = adw[t];
    int w = t >> 5, lane = t & 31;
#pragma unroll
    for (int j = 0; j < NB1; j++) {
        float ps = acc[j] * aw;
        float pd = acc[j] * dw;
#pragma unroll
        for (int o = 16; o > 0; o >>= 1) {
            ps += __shfl_down_sync(0xffffffffu, ps, o);
            pd += __shfl_down_sync(0xffffffffu, pd, o);
        }
        if (lane == 0) { ss[w][j] = ps; sd[w][j] = pd; }
    }
    __syncthreads();
    if (t < NB1 * HEADS) {              // node j = t>>2, head h = t&3
        int j = t >> 2, h = t & 3;
        int n = nb + j;
        if (n < NN) {
            g_as1[n * HEADS + h] = ss[2 * h][j] + ss[2 * h + 1][j];
            g_ad1[n * HEADS + h] = sd[2 * h][j] + sd[2 * h + 1][j];
        }
    }
}

// exp(leaky_relu(e)) per edge (logits O(1): no max shift; __expf: 2-ulp,
// budget 1e-3), store, vector-RED denominators.
__global__ void k_exp1() {
    int idx = blockIdx.x * blockDim.x + threadIdx.x;
    if (idx >= ETOT) return;
    int s = g_src[idx], d = g_dst[idx];
    float4 a = *(const float4*)&g_as1[s * 4];
    float4 b = *(const float4*)&g_ad1[d * 4];
    float4 e;
    e.x = __expf(lrelu(a.x + b.x));
    e.y = __expf(lrelu(a.y + b.y));
    e.z = __expf(lrelu(a.z + b.z));
    e.w = __expf(lrelu(a.w + b.w));
    *(float4*)&g_ex1[idx * 4] = e;
    atomicAdd((float4*)&g_dn1[d * 4], e);
}

// Per-node reciprocal folds (division hoisted out of the per-edge scatters).
__global__ void k_rcp1() {
    int i = blockIdx.x * blockDim.x + threadIdx.x;
    if (i < NN * HEADS) g_dn1[i] = 0.25f / (g_dn1[i] + 1e-16f);
}
__global__ void k_rcp2() {
    int i = blockIdx.x * blockDim.x + threadIdx.x;
    if (i < NN) g_dn2[i] = 1.0f / (g_dn2[i] + 1e-16f);
}

// message scatter (layer 1): HALF-warp per edge, float4 lanes, head-mean fused.
// Per edge: 4x LDG.128 gather + 1x RED.128 (was 8x LDG.64 + 2x RED.64).
__global__ void k_scat1() {
    int gt = blockIdx.x * blockDim.x + threadIdx.x;
    int e = gt >> 4, l16 = gt & 15;                // 16 lanes per edge
    if (e >= ETOT) return;
    int s = g_src[e], d = g_dst[e];
    float4 ex = *(const float4*)&g_ex1[e * 4];     // broadcast within half-warp
    float4 rc = *(const float4*)&g_dn1[d * 4];     // already 0.25/denom
    float a0 = ex.x * rc.x;
    float a1 = ex.y * rc.y;
    float a2 = ex.z * rc.z;
    float a3 = ex.w * rc.w;
    const float4* hp = (const float4*)&g_h1[s * C1];   // [4 heads][16 float4]
    float4 v0 = hp[l16];
    float4 v1 = hp[16 + l16];
    float4 v2 = hp[32 + l16];
    float4 v3 = hp[48 + l16];
    float4 v;
    v.x = a0 * v0.x + a1 * v1.x + a2 * v2.x + a3 * v3.x;
    v.y = a0 * v0.y + a1 * v1.y + a2 * v2.y + a3 * v3.y;
    v.z = a0 * v0.z + a1 * v1.z + a2 * v2.z + a3 * v3.z;
    v.w = a0 * v0.w + a1 * v1.w + a2 * v2.w + a3 * v3.w;
    atomicAdd((float4*)&g_out1[d * HID] + l16, v);
}

// h2 = elu(out1 + b1) @ W2 (64 -> 64) + attention dots. 16 nodes/block.
#define NB2 16
__global__ void k_gemm2(const float* __restrict__ W, const float* __restrict__ b1,
                        const float* __restrict__ asw, const float* __restrict__ adw) {
    int t = threadIdx.x;
    int sub = t >> 6, tc = t & 63;      // 4 subs x 64 channels
    int nb = blockIdx.x * NB2;
    __shared__ float xs[NB2][65];       // padded
    __shared__ float ss[8][4], sd[8][4]; // [warp][node-within-sub]
    for (int j = t; j < NB2 * 64; j += 256) {
        int n = nb + (j >> 6);
        xs[j >> 6][j & 63] = (n < NN) ? elu_f(g_out1[n * 64 + (j & 63)] + b1[j & 63]) : 0.f;
    }
    __syncthreads();
    float acc[4] = {0.f, 0.f, 0.f, 0.f};
#pragma unroll 8
    for (int k = 0; k < 64; k++) {
        float wv = W[k * 64 + tc];
#pragma unroll
        for (int j = 0; j < 4; j++) acc[j] = fmaf(xs[sub * 4 + j][k], wv, acc[j]);
    }
    float aw = asw[tc], dw = adw[tc];
    int w = t >> 5, lane = t & 31;
#pragma unroll
    for (int j = 0; j < 4; j++) {
        int n = nb + sub * 4 + j;
        if (n < NN) g_h2[n * 64 + tc] = acc[j];
        float ps = acc[j] * aw;
        float pd = acc[j] * dw;
#pragma unroll
        for (int o = 16; o > 0; o >>= 1) {
            ps += __shfl_down_sync(0xffffffffu, ps, o);
            pd += __shfl_down_sync(0xffffffffu, pd, o);
        }
        if (lane == 0) { ss[w][j] = ps; sd[w][j] = pd; }
    }
    __syncthreads();
    if (t < NB2) {
        int n = nb + t;
        if (n < NN) {
            int wbase = 2 * (t >> 2);    // two warps per sub
            g_as2[n] = ss[wbase][t & 3] + ss[wbase + 1][t & 3];
            g_ad2[n] = sd[wbase][t & 3] + sd[wbase + 1][t & 3];
        }
    }
}

__global__ void k_exp2() {
    int idx = blockIdx.x * blockDim.x + threadIdx.x;
    if (idx >= ETOT) return;
    int s = g_src[idx], d = g_dst[idx];
    float ex = __expf(lrelu(g_as2[s] + g_ad2[d]));
    g_ex2[idx] = ex;
    atomicAdd(&g_dn2[d], ex);
}

// message scatter (layer 2): HALF-warp per edge, float4 lanes.
// Per edge: 1x LDG.128 + 1x RED.128.
__global__ void k_scat2() {
    int gt = blockIdx.x * blockDim.x + threadIdx.x;
    int e = gt >> 4, l16 = gt & 15;
    if (e >= ETOT) return;
    int s = g_src[e], d = g_dst[e];
    float alpha = g_ex2[e] * g_dn2[d];             // dn2 already reciprocal
    float4 h = ((const float4*)&g_h2[s * 64])[l16];
    float4 v;
    v.x = alpha * h.x; v.y = alpha * h.y; v.z = alpha * h.z; v.w = alpha * h.w;
    atomicAdd((float4*)&g_out2[d * 64] + l16, v);
}

__global__ void k_fin2(const float* __restrict__ b2, float* __restrict__ out) {
    int i = blockIdx.x * blockDim.x + threadIdx.x;
    if (i >= NN * HID) return;
    out[i] = elu_f(g_out2[i] + b2[i & 63]);
}

// ---------------- launch ----------------
extern "C" void kernel_launch(void* const* d_in, const int* in_sizes, int n_in,
                              void* d_out, int out_size) {
    const float* x    = (const float*)d_in[0];
    const void*  ei   = d_in[1];               // int32 or int64, detected on device
    const float* W1   = (const float*)d_in[2];
    const float* as1w = (const float*)d_in[3];
    const float* ad1w = (const float*)d_in[4];
    const float* b1   = (const float*)d_in[5];
    const float* W2   = (const float*)d_in[6];
    const float* as2w = (const float*)d_in[7];
    const float* ad2w = (const float*)d_in[8];
    const float* b2   = (const float*)d_in[9];
    float*       out  = (float*)d_out;

    const int TB = 256;
    int edge_blocks  = (ETOT + TB - 1) / TB;                 // thread per edge
    int hwarp_blocks = (ETOT * 16 + TB - 1) / TB;            // half-warp per edge
    int node_blocks  = (NN * HID + TB - 1) / TB;

    k_prep<<<2048, TB>>>(ei);
    k_gemm1<<<(NN + NB1 - 1) / NB1, TB>>>(x, W1, as1w, ad1w);
    k_exp1<<<edge_blocks, TB>>>();
    k_rcp1<<<(NN * HEADS + TB - 1) / TB, TB>>>();
    k_scat1<<<hwarp_blocks, TB>>>();
    k_gemm2<<<(NN + NB2 - 1) / NB2, TB>>>(W2, b1, as2w, ad2w);
    k_exp2<<<edge_blocks, TB>>>();
    k_rcp2<<<(NN + TB - 1) / TB, TB>>>();
    k_scat2<<<hwarp_blocks, TB>>>();
    k_fin2<<<node_blocks, TB>>>(b2, out);
}

// round 12
// speedup vs baseline: 1.2216x; 1.0038x over previous
#include <cuda_runtime.h>
#include <math.h>

// Problem constants (fixed by the dataset)
#define NN   50000
#define EE   400000
#define ETOT (EE + NN)          // edges + self loops
#define HID  64
#define HEADS 4
#define C1   (HEADS * HID)      // 256

// ---------------- scratch (no allocation allowed -> __device__ globals) -------------
__device__ int g_src[ETOT];                       // decoded int32 edge endpoints
__device__ int g_dst[ETOT];

__device__ __align__(16) float g_h1[NN * C1];     // layer1 features per head  [N,4,64]
__device__ __align__(16) float g_out1[NN * HID];  // layer1 head-mean accumulator [N,64]
__device__ __align__(16) float g_as1[NN * HEADS]; // a_src [N,4]
__device__ __align__(16) float g_ad1[NN * HEADS]; // a_dst [N,4]
__device__ __align__(16) float g_dn1[NN * HEADS]; // denom -> 0.25/denom after k_rcp1
__device__ __align__(16) float g_ex1[ETOT * HEADS]; // per-edge exp values

__device__ __align__(16) float g_h2[NN * HID];    // layer2 features
__device__ float g_as2[NN];
__device__ float g_ad2[NN];
__device__ float g_dn2[NN];                       // raw layer2 denominators
__device__ __align__(16) float g_out2[NN * HID];  // unnormalized layer2 messages

// ---------------- helpers ----------------
__device__ __forceinline__ float lrelu(float x) { return x > 0.f ? x : 0.2f * x; }
__device__ __forceinline__ float elu_f(float x) { return x > 0.f ? x : expm1f(x); }
__device__ __forceinline__ int clampN(int v) { return v < 0 ? 0 : (v >= NN ? NN - 1 : v); }

// ---------------- kernels ----------------

// Decode edge index (either dtype -> int32, self loops appended) + zero
// accumulators. Dtype detected locally from the first 16 values (128B, L2-hot).
// Indices clamped into [0, NN): mismatch surfaces as rel_err, never as IMA.
__global__ void k_prep(const void* ei) {
    const long long* p64 = (const long long*)ei;
    int is64 = 1;
#pragma unroll
    for (int k = 0; k < 16; k++) {
        long long v = p64[k];
        if (v < 0 || v >= NN) is64 = 0;
    }
    int i = blockIdx.x * blockDim.x + threadIdx.x;
    int stride = gridDim.x * blockDim.x;
    if (is64) {
        for (int j = i; j < ETOT; j += stride) {
            if (j < EE) { g_src[j] = clampN((int)p64[j]); g_dst[j] = clampN((int)p64[EE + j]); }
            else        { g_src[j] = g_dst[j] = j - EE; }
        }
    } else {
        const int* p = (const int*)ei;
        for (int j = i; j < ETOT; j += stride) {
            if (j < EE) { g_src[j] = clampN(p[j]); g_dst[j] = clampN(p[EE + j]); }
            else        { g_src[j] = g_dst[j] = j - EE; }
        }
    }
    for (int j = i; j < NN * HID; j += stride) { g_out1[j] = 0.f; g_out2[j] = 0.f; }
    for (int j = i; j < NN * HEADS; j += stride) g_dn1[j] = 0.f;
    for (int j = i; j < NN; j += stride)         g_dn2[j] = 0.f;
}

// h1 = x @ W1 (16 -> 256) + per-head attention dots. 16 nodes/block, W1 reused
// across 16 node accumulators.
#define NB1 16
__global__ void k_gemm1(const float* __restrict__ x, const float* __restrict__ W,
                        const float* __restrict__ asw, const float* __restrict__ adw) {
    int t = threadIdx.x;                // channel 0..255
    int nb = blockIdx.x * NB1;
    __shared__ float xs[NB1][16];
    __shared__ float ss[8][NB1], sd[8][NB1];   // [warp][node]
    if (t < NB1 * 16) {
        int n = nb + (t >> 4);
        xs[t >> 4][t & 15] = (n < NN) ? x[n * 16 + (t & 15)] : 0.f;
    }
    __syncthreads();
    float acc[NB1];
#pragma unroll
    for (int j = 0; j < NB1; j++) acc[j] = 0.f;
#pragma unroll
    for (int k = 0; k < 16; k++) {
        float wv = W[k * C1 + t];
#pragma unroll
        for (int j = 0; j < NB1; j++) acc[j] = fmaf(xs[j][k], wv, acc[j]);
    }
#pragma unroll
    for (int j = 0; j < NB1; j++) {
        int n = nb + j;
        if (n < NN) g_h1[n * C1 + t] = acc[j];
    }
    float aw = asw[t], dw = adw[t];
    int w = t >> 5, lane = t & 31;
#pragma unroll
    for (int j = 0; j < NB1; j++) {
        float ps = acc[j] * aw;
        float pd = acc[j] * dw;
#pragma unroll
        for (int o = 16; o > 0; o >>= 1) {
            ps += __shfl_down_sync(0xffffffffu, ps, o);
            pd += __shfl_down_sync(0xffffffffu, pd, o);
        }
        if (lane == 0) { ss[w][j] = ps; sd[w][j] = pd; }
    }
    __syncthreads();
    if (t < NB1 * HEADS) {              // 64 writes: node j = t>>2, head h = t&3
        int j = t >> 2, h = t & 3;
        int n = nb + j;
        if (n < NN) {
            g_as1[n * HEADS + h] = ss[2 * h][j] + ss[2 * h + 1][j];
            g_ad1[n * HEADS + h] = sd[2 * h][j] + sd[2 * h + 1][j];
        }
    }
}

// exp(leaky_relu(e)) per edge (logits O(1): no max shift; __expf: 2-ulp,
// budget 1e-3), store, vector-RED denominators.
__global__ void k_exp1() {
    int idx = blockIdx.x * blockDim.x + threadIdx.x;
    if (idx >= ETOT) return;
    int s = g_src[idx], d = g_dst[idx];
    float4 a = *(const float4*)&g_as1[s * 4];
    float4 b = *(const float4*)&g_ad1[d * 4];
    float4 e;
    e.x = __expf(lrelu(a.x + b.x));
    e.y = __expf(lrelu(a.y + b.y));
    e.z = __expf(lrelu(a.z + b.z));
    e.w = __expf(lrelu(a.w + b.w));
    *(float4*)&g_ex1[idx * 4] = e;
    atomicAdd((float4*)&g_dn1[d * 4], e);
}

// Per-node reciprocal fold for layer 1 (division hoisted out of k_scat1).
__global__ void k_rcp1() {
    int i = blockIdx.x * blockDim.x + threadIdx.x;
    if (i < NN * HEADS) g_dn1[i] = 0.25f / (g_dn1[i] + 1e-16f);
}

// message scatter (layer 1): HALF-warp per edge, float4 lanes, head-mean fused.
// Per edge: 4x LDG.128 gather + 1x RED.128.
__global__ void k_scat1() {
    int gt = blockIdx.x * blockDim.x + threadIdx.x;
    int e = gt >> 4, l16 = gt & 15;                // 16 lanes per edge
    if (e >= ETOT) return;
    int s = g_src[e], d = g_dst[e];
    float4 ex = *(const float4*)&g_ex1[e * 4];     // broadcast within half-warp
    float4 rc = *(const float4*)&g_dn1[d * 4];     // already 0.25/denom
    float a0 = ex.x * rc.x;
    float a1 = ex.y * rc.y;
    float a2 = ex.z * rc.z;
    float a3 = ex.w * rc.w;
    const float4* hp = (const float4*)&g_h1[s * C1];   // [4 heads][16 float4]
    float4 v0 = hp[l16];
    float4 v1 = hp[16 + l16];
    float4 v2 = hp[32 + l16];
    float4 v3 = hp[48 + l16];
    float4 v;
    v.x = a0 * v0.x + a1 * v1.x + a2 * v2.x + a3 * v3.x;
    v.y = a0 * v0.y + a1 * v1.y + a2 * v2.y + a3 * v3.y;
    v.z = a0 * v0.z + a1 * v1.z + a2 * v2.z + a3 * v3.z;
    v.w = a0 * v0.w + a1 * v1.w + a2 * v2.w + a3 * v3.w;
    atomicAdd((float4*)&g_out1[d * HID] + l16, v);
}

// h2 = elu(out1 + b1) @ W2 (64 -> 64) + attention dots. 16 nodes/block.
#define NB2 16
__global__ void k_gemm2(const float* __restrict__ W, const float* __restrict__ b1,
                        const float* __restrict__ asw, const float* __restrict__ adw) {
    int t = threadIdx.x;
    int sub = t >> 6, tc = t & 63;      // 4 subs x 64 channels
    int nb = blockIdx.x * NB2;
    __shared__ float xs[NB2][65];       // padded
    __shared__ float ss[8][4], sd[8][4]; // [warp][node-within-sub]
    for (int j = t; j < NB2 * 64; j += 256) {
        int n = nb + (j >> 6);
        xs[j >> 6][j & 63] = (n < NN) ? elu_f(g_out1[n * 64 + (j & 63)] + b1[j & 63]) : 0.f;
    }
    __syncthreads();
    float acc[4] = {0.f, 0.f, 0.f, 0.f};
#pragma unroll 8
    for (int k = 0; k < 64; k++) {
        float wv = W[k * 64 + tc];
#pragma unroll
        for (int j = 0; j < 4; j++) acc[j] = fmaf(xs[sub * 4 + j][k], wv, acc[j]);
    }
    float aw = asw[tc], dw = adw[tc];
    int w = t >> 5, lane = t & 31;
#pragma unroll
    for (int j = 0; j < 4; j++) {
        int n = nb + sub * 4 + j;
        if (n < NN) g_h2[n * 64 + tc] = acc[j];
        float ps = acc[j] * aw;
        float pd = acc[j] * dw;
#pragma unroll
        for (int o = 16; o > 0; o >>= 1) {
            ps += __shfl_down_sync(0xffffffffu, ps, o);
            pd += __shfl_down_sync(0xffffffffu, pd, o);
        }
        if (lane == 0) { ss[w][j] = ps; sd[w][j] = pd; }
    }
    __syncthreads();
    if (t < NB2) {
        int n = nb + t;
        if (n < NN) {
            int wbase = 2 * (t >> 2);    // two warps per sub
            g_as2[n] = ss[wbase][t & 3] + ss[wbase + 1][t & 3];
            g_ad2[n] = sd[wbase][t & 3] + sd[wbase + 1][t & 3];
        }
    }
}

// FUSED layer-2 edge pass (deferred normalization): per edge, compute
// ex = exp(lrelu(as2[s]+ad2[d])) in-register, scatter UNNORMALIZED ex*h into
// out2 and ex into dn2. Normalization happens per-node in k_fin2.
// Per edge: 2 scalar bcast loads + 1x LDG.128 + 1x RED.128 + 1x RED.32.
__global__ void k_scat2f() {
    int gt = blockIdx.x * blockDim.x + threadIdx.x;
    int e = gt >> 4, l16 = gt & 15;
    if (e >= ETOT) return;
    int s = g_src[e], d = g_dst[e];
    float ex = __expf(lrelu(g_as2[s] + g_ad2[d]));
    float4 h = ((const float4*)&g_h2[s * 64])[l16];
    float4 v;
    v.x = ex * h.x; v.y = ex * h.y; v.z = ex * h.z; v.w = ex * h.w;
    atomicAdd((float4*)&g_out2[d * 64] + l16, v);
    if (l16 == 0) atomicAdd(&g_dn2[d], ex);
}

// Final: normalize by per-node denominator (computed here, no separate rcp
// pass), add bias, ELU. dn2 load is 64-way broadcast per node.
__global__ void k_fin2(const float* __restrict__ b2, float* __restrict__ out) {
    int i = blockIdx.x * blockDim.x + threadIdx.x;
    if (i >= NN * HID) return;
    float inv = 1.0f / (g_dn2[i >> 6] + 1e-16f);
    out[i] = elu_f(g_out2[i] * inv + b2[i & 63]);
}

// ---------------- launch ----------------
extern "C" void kernel_launch(void* const* d_in, const int* in_sizes, int n_in,
                              void* d_out, int out_size) {
    const float* x    = (const float*)d_in[0];
    const void*  ei   = d_in[1];               // int32 or int64, detected on device
    const float* W1   = (const float*)d_in[2];
    const float* as1w = (const float*)d_in[3];
    const float* ad1w = (const float*)d_in[4];
    const float* b1   = (const float*)d_in[5];
    const float* W2   = (const float*)d_in[6];
    const float* as2w = (const float*)d_in[7];
    const float* ad2w = (const float*)d_in[8];
    const float* b2   = (const float*)d_in[9];
    float*       out  = (float*)d_out;

    const int TB = 256;
    int edge_blocks  = (ETOT + TB - 1) / TB;                 // thread per edge
    int hwarp_blocks = (ETOT * 16 + TB - 1) / TB;            // half-warp per edge
    int node_blocks  = (NN * HID + TB - 1) / TB;

    k_prep<<<2048, TB>>>(ei);
    k_gemm1<<<(NN + NB1 - 1) / NB1, TB>>>(x, W1, as1w, ad1w);
    k_exp1<<<edge_blocks, TB>>>();
    k_rcp1<<<(NN * HEADS + TB - 1) / TB, TB>>>();
    k_scat1<<<hwarp_blocks, TB>>>();
    k_gemm2<<<(NN + NB2 - 1) / NB2, TB>>>(W2, b1, as2w, ad2w);
    k_scat2f<<<hwarp_blocks, TB>>>();
    k_fin2<<<node_blocks, TB>>>(b2, out);
}

// round 13
// speedup vs baseline: 1.3988x; 1.1451x over previous
#include <cuda_runtime.h>
#include <cuda_fp16.h>
#include <math.h>

// Problem constants (fixed by the dataset)
#define NN   50000
#define EE   400000
#define ETOT (EE + NN)          // edges + self loops
#define HID  64
#define HEADS 4
#define C1   (HEADS * HID)      // 256

// ---------------- scratch (no allocation allowed -> __device__ globals) -------------
__device__ int g_src[ETOT];
__device__ int g_dst[ETOT];

__device__ __align__(16) __half g_h1h[NN * C1];   // layer1 features, fp16 [N,4,64]
__device__ __align__(16) float g_out1[NN * HID];  // layer1 head-mean accumulator [N,64]
__device__ __align__(16) float g_as1[NN * HEADS]; // a_src [N,4]
__device__ __align__(16) float g_ad1[NN * HEADS]; // a_dst [N,4]
__device__ __align__(16) float g_dn1[NN * HEADS]; // denom -> 0.25/denom after k_rcp1
__device__ __align__(16) float g_ex1[ETOT * HEADS]; // per-edge exp values

__device__ __align__(16) float g_h2[NN * HID];    // layer2 features (fp32)
__device__ float g_as2[NN];
__device__ float g_ad2[NN];
__device__ float g_dn2[NN];                       // raw layer2 denominators
__device__ __align__(16) float g_out2[NN * HID];  // unnormalized layer2 messages

// Hoisted attention-weight projections: a_src = x·(W att)
__device__ float g_wa1[16 * HEADS];               // [k][h]
__device__ float g_wd1[16 * HEADS];
__device__ float g_wa2[HID];
__device__ float g_wd2[HID];

// ---------------- helpers ----------------
__device__ __forceinline__ float lrelu(float x) { return x > 0.f ? x : 0.2f * x; }
__device__ __forceinline__ float elu_f(float x) { return x > 0.f ? x : expm1f(x); }
__device__ __forceinline__ int clampN(int v) { return v < 0 ? 0 : (v >= NN ? NN - 1 : v); }
__device__ __forceinline__ float4 h4_to_f4(uint2 r) {
    __half2 a = *(__half2*)&r.x, b = *(__half2*)&r.y;
    float2 lo = __half22float2(a), hi = __half22float2(b);
    return make_float4(lo.x, lo.y, hi.x, hi.y);
}

// ---------------- kernels ----------------

// Decode edge index (dtype auto-detected from first 16 values), zero
// accumulators, and (block 0) precompute the hoisted attention projections
// WA = W·att_src, WD = W·att_dst for both layers.
__global__ void k_prep(const void* ei, const float* __restrict__ W1,
                       const float* __restrict__ as1w, const float* __restrict__ ad1w,
                       const float* __restrict__ W2,
                       const float* __restrict__ as2w, const float* __restrict__ ad2w) {
    if (blockIdx.x == 0) {
        int t = threadIdx.x;
        if (t < 64) {                    // WA1/WD1: k = t>>2, h = t&3
            int k = t >> 2, h = t & 3;
            float sa = 0.f, sd = 0.f;
            for (int c = 0; c < HID; c++) {
                float w = W1[k * C1 + h * HID + c];
                sa = fmaf(w, as1w[h * HID + c], sa);
                sd = fmaf(w, ad1w[h * HID + c], sd);
            }
            g_wa1[k * HEADS + h] = sa;
            g_wd1[k * HEADS + h] = sd;
        } else if (t < 128) {            // WA2/WD2: k = t-64
            int k = t - 64;
            float sa = 0.f, sd = 0.f;
            for (int c = 0; c < HID; c++) {
                float w = W2[k * HID + c];
                sa = fmaf(w, as2w[c], sa);
                sd = fmaf(w, ad2w[c], sd);
            }
            g_wa2[k] = sa;
            g_wd2[k] = sd;
        }
    }
    const long long* p64 = (const long long*)ei;
    int is64 = 1;
#pragma unroll
    for (int k = 0; k < 16; k++) {
        long long v = p64[k];
        if (v < 0 || v >= NN) is64 = 0;
    }
    int i = blockIdx.x * blockDim.x + threadIdx.x;
    int stride = gridDim.x * blockDim.x;
    if (is64) {
        for (int j = i; j < ETOT; j += stride) {
            if (j < EE) { g_src[j] = clampN((int)p64[j]); g_dst[j] = clampN((int)p64[EE + j]); }
            else        { g_src[j] = g_dst[j] = j - EE; }
        }
    } else {
        const int* p = (const int*)ei;
        for (int j = i; j < ETOT; j += stride) {
            if (j < EE) { g_src[j] = clampN(p[j]); g_dst[j] = clampN(p[EE + j]); }
            else        { g_src[j] = g_dst[j] = j - EE; }
        }
    }
    for (int j = i; j < NN * HID; j += stride) { g_out1[j] = 0.f; g_out2[j] = 0.f; }
    for (int j = i; j < NN * HEADS; j += stride) g_dn1[j] = 0.f;
    for (int j = i; j < NN; j += stride)         g_dn2[j] = 0.f;
}

// h1 = x @ W1 (16 -> 256, stored fp16) + attention dots via hoisted WA/WD
// (no shfl reductions). 16 nodes/block, W1 value reused across 16 accumulators.
#define NB1 16
__global__ void k_gemm1(const float* __restrict__ x, const float* __restrict__ W) {
    int t = threadIdx.x;                // channel 0..255
    int nb = blockIdx.x * NB1;
    __shared__ float xs[NB1][16];
    if (t < NB1 * 16) {
        int n = nb + (t >> 4);
        xs[t >> 4][t & 15] = (n < NN) ? x[n * 16 + (t & 15)] : 0.f;
    }
    __syncthreads();
    float acc[NB1];
#pragma unroll
    for (int j = 0; j < NB1; j++) acc[j] = 0.f;
#pragma unroll
    for (int k = 0; k < 16; k++) {
        float wv = W[k * C1 + t];
#pragma unroll
        for (int j = 0; j < NB1; j++) acc[j] = fmaf(xs[j][k], wv, acc[j]);
    }
#pragma unroll
    for (int j = 0; j < NB1; j++) {
        int n = nb + j;
        if (n < NN) g_h1h[n * C1 + t] = __float2half(acc[j]);
    }
    // attention dots from xs via hoisted projections: 64 threads, 16 FMA each
    if (t < NB1 * HEADS) {
        int j = t >> 2, h = t & 3;
        int n = nb + j;
        if (n < NN) {
            float sa = 0.f, sd = 0.f;
#pragma unroll
            for (int k = 0; k < 16; k++) {
                float xv = xs[j][k];
                sa = fmaf(xv, g_wa1[k * HEADS + h], sa);
                sd = fmaf(xv, g_wd1[k * HEADS + h], sd);
            }
            g_as1[n * HEADS + h] = sa;
            g_ad1[n * HEADS + h] = sd;
        }
    }
}

// exp(leaky_relu(e)) per edge (logits O(1): no max shift; __expf), store,
// vector-RED denominators.
__global__ void k_exp1() {
    int idx = blockIdx.x * blockDim.x + threadIdx.x;
    if (idx >= ETOT) return;
    int s = g_src[idx], d = g_dst[idx];
    float4 a = *(const float4*)&g_as1[s * 4];
    float4 b = *(const float4*)&g_ad1[d * 4];
    float4 e;
    e.x = __expf(lrelu(a.x + b.x));
    e.y = __expf(lrelu(a.y + b.y));
    e.z = __expf(lrelu(a.z + b.z));
    e.w = __expf(lrelu(a.w + b.w));
    *(float4*)&g_ex1[idx * 4] = e;
    atomicAdd((float4*)&g_dn1[d * 4], e);
}

// Per-node reciprocal fold for layer 1.
__global__ void k_rcp1() {
    int i = blockIdx.x * blockDim.x + threadIdx.x;
    if (i < NN * HEADS) g_dn1[i] = 0.25f / (g_dn1[i] + 1e-16f);
}

// message scatter (layer 1): HALF-warp per edge, fp16 gathers (half the
// sector traffic of fp32), head-mean fused. Per edge: 64x LDG.64 + 16x RED.128.
__global__ void k_scat1() {
    int gt = blockIdx.x * blockDim.x + threadIdx.x;
    int e = gt >> 4, l16 = gt & 15;                // 16 lanes per edge
    if (e >= ETOT) return;
    int s = g_src[e], d = g_dst[e];
    float4 ex = *(const float4*)&g_ex1[e * 4];     // broadcast within half-warp
    float4 rc = *(const float4*)&g_dn1[d * 4];     // already 0.25/denom
    float a0 = ex.x * rc.x;
    float a1 = ex.y * rc.y;
    float a2 = ex.z * rc.z;
    float a3 = ex.w * rc.w;
    const __half* hp = &g_h1h[s * C1 + 4 * l16];   // channels 4*l16..+3
    float4 f0 = h4_to_f4(*(const uint2*)(hp));
    float4 f1 = h4_to_f4(*(const uint2*)(hp + 64));
    float4 f2 = h4_to_f4(*(const uint2*)(hp + 128));
    float4 f3 = h4_to_f4(*(const uint2*)(hp + 192));
    float4 v;
    v.x = a0 * f0.x + a1 * f1.x + a2 * f2.x + a3 * f3.x;
    v.y = a0 * f0.y + a1 * f1.y + a2 * f2.y + a3 * f3.y;
    v.z = a0 * f0.z + a1 * f1.z + a2 * f2.z + a3 * f3.z;
    v.w = a0 * f0.w + a1 * f1.w + a2 * f2.w + a3 * f3.w;
    atomicAdd((float4*)&g_out1[d * HID + 4 * l16], v);
}

// h2 = elu(out1 + b1) @ W2 (64 -> 64) + attention dots via WA2/WD2.
// 16 nodes/block; layer-1 epilogue fused into the smem staging load.
#define NB2 16
__global__ void k_gemm2(const float* __restrict__ W, const float* __restrict__ b1) {
    int t = threadIdx.x;
    int sub = t >> 6, tc = t & 63;      // 4 subs x 64 channels
    int nb = blockIdx.x * NB2;
    __shared__ float xs[NB2][65];       // padded
    for (int j = t; j < NB2 * 64; j += 256) {
        int n = nb + (j >> 6);
        xs[j >> 6][j & 63] = (n < NN) ? elu_f(g_out1[n * 64 + (j & 63)] + b1[j & 63]) : 0.f;
    }
    __syncthreads();
    float acc[4] = {0.f, 0.f, 0.f, 0.f};
#pragma unroll 8
    for (int k = 0; k < 64; k++) {
        float wv = W[k * 64 + tc];
#pragma unroll
        for (int j = 0; j < 4; j++) acc[j] = fmaf(xs[sub * 4 + j][k], wv, acc[j]);
    }
#pragma unroll
    for (int j = 0; j < 4; j++) {
        int n = nb + sub * 4 + j;
        if (n < NN) g_h2[n * 64 + tc] = acc[j];
    }
    // attention dots: 16 threads, 64 FMA x2 each, from smem + hoisted WA2/WD2
    if (t < NB2) {
        int n = nb + t;
        if (n < NN) {
            float sa = 0.f, sd = 0.f;
#pragma unroll 8
            for (int k = 0; k < 64; k++) {
                float xv = xs[t][k];
                sa = fmaf(xv, g_wa2[k], sa);
                sd = fmaf(xv, g_wd2[k], sd);
            }
            g_as2[n] = sa;
            g_ad2[n] = sd;
        }
    }
}

// FUSED layer-2 edge pass (deferred normalization): scatter unnormalized
// ex*h into out2 and ex into dn2; normalize per-node in k_fin2.
__global__ void k_scat2f() {
    int gt = blockIdx.x * blockDim.x + threadIdx.x;
    int e = gt >> 4, l16 = gt & 15;
    if (e >= ETOT) return;
    int s = g_src[e], d = g_dst[e];
    float ex = __expf(lrelu(g_as2[s] + g_ad2[d]));
    float4 h = ((const float4*)&g_h2[s * 64])[l16];
    float4 v;
    v.x = ex * h.x; v.y = ex * h.y; v.z = ex * h.z; v.w = ex * h.w;
    atomicAdd((float4*)&g_out2[d * 64] + l16, v);
    if (l16 == 0) atomicAdd(&g_dn2[d], ex);
}

// Final: normalize by per-node denominator, add bias, ELU.
__global__ void k_fin2(const float* __restrict__ b2, float* __restrict__ out) {
    int i = blockIdx.x * blockDim.x + threadIdx.x;
    if (i >= NN * HID) return;
    float inv = 1.0f / (g_dn2[i >> 6] + 1e-16f);
    out[i] = elu_f(g_out2[i] * inv + b2[i & 63]);
}

// ---------------- launch ----------------
extern "C" void kernel_launch(void* const* d_in, const int* in_sizes, int n_in,
                              void* d_out, int out_size) {
    const float* x    = (const float*)d_in[0];
    const void*  ei   = d_in[1];               // int32 or int64, detected on device
    const float* W1   = (const float*)d_in[2];
    const float* as1w = (const float*)d_in[3];
    const float* ad1w = (const float*)d_in[4];
    const float* b1   = (const float*)d_in[5];
    const float* W2   = (const float*)d_in[6];
    const float* as2w = (const float*)d_in[7];
    const float* ad2w = (const float*)d_in[8];
    const float* b2   = (const float*)d_in[9];
    float*       out  = (float*)d_out;

    const int TB = 256;
    int edge_blocks  = (ETOT + TB - 1) / TB;                 // thread per edge
    int hwarp_blocks = (ETOT * 16 + TB - 1) / TB;            // half-warp per edge
    int node_blocks  = (NN * HID + TB - 1) / TB;

    k_prep<<<2048, TB>>>(ei, W1, as1w, ad1w, W2, as2w, ad2w);
    k_gemm1<<<(NN + NB1 - 1) / NB1, TB>>>(x, W1);
    k_exp1<<<edge_blocks, TB>>>();
    k_rcp1<<<(NN * HEADS + TB - 1) / TB, TB>>>();
    k_scat1<<<hwarp_blocks, TB>>>();
    k_gemm2<<<(NN + NB2 - 1) / NB2, TB>>>(W2, b1);
    k_scat2f<<<hwarp_blocks, TB>>>();
    k_fin2<<<node_blocks, TB>>>(b2, out);
}

// round 14
// speedup vs baseline: 1.4150x; 1.0116x over previous
#include <cuda_runtime.h>
#include <cuda_fp16.h>
#include <math.h>

// Problem constants (fixed by the dataset)
#define NN   50000
#define EE   400000
#define ETOT (EE + NN)          // edges + self loops
#define HID  64
#define HEADS 4
#define C1   (HEADS * HID)      // 256

// ---------------- scratch (no allocation allowed -> __device__ globals) -------------
__device__ int g_src[ETOT];
__device__ int g_dst[ETOT];

__device__ __align__(16) __half g_h1h[NN * C1];   // layer1 features, fp16 [N,4,64]
__device__ __align__(16) float g_out1[NN * HID];  // layer1 head-mean accumulator [N,64]
__device__ __align__(16) float g_as1[NN * HEADS]; // a_src [N,4]
__device__ __align__(16) float g_ad1[NN * HEADS]; // a_dst [N,4]
__device__ __align__(16) float g_dn1[NN * HEADS]; // denom -> 0.25/denom after k_rcp1
__device__ __align__(16) float g_ex1[ETOT * HEADS]; // per-edge exp values

__device__ __align__(16) __half g_h2h[NN * HID];  // layer2 features, fp16
__device__ float g_as2[NN];
__device__ float g_ad2[NN];
__device__ float g_dn2[NN];                       // raw layer2 denominators
__device__ __align__(16) float g_out2[NN * HID];  // unnormalized layer2 messages

// Hoisted attention-weight projections: a_src = x·(W att)
__device__ float g_wa1[16 * HEADS];               // [k][h]
__device__ float g_wd1[16 * HEADS];
__device__ float g_wa2[HID];
__device__ float g_wd2[HID];

// ---------------- helpers ----------------
__device__ __forceinline__ float lrelu(float x) { return x > 0.f ? x : 0.2f * x; }
__device__ __forceinline__ float elu_f(float x) { return x > 0.f ? x : expm1f(x); }
__device__ __forceinline__ int clampN(int v) { return v < 0 ? 0 : (v >= NN ? NN - 1 : v); }
__device__ __forceinline__ float4 h4_to_f4(uint2 r) {
    __half2 a = *(__half2*)&r.x, b = *(__half2*)&r.y;
    float2 lo = __half22float2(a), hi = __half22float2(b);
    return make_float4(lo.x, lo.y, hi.x, hi.y);
}

// ---------------- kernels ----------------

// Decode edge index (dtype auto-detected from first 16 values), zero
// accumulators, and (block 0) precompute hoisted attention projections.
__global__ void k_prep(const void* ei, const float* __restrict__ W1,
                       const float* __restrict__ as1w, const float* __restrict__ ad1w,
                       const float* __restrict__ W2,
                       const float* __restrict__ as2w, const float* __restrict__ ad2w) {
    if (blockIdx.x == 0) {
        int t = threadIdx.x;
        if (t < 64) {                    // WA1/WD1: k = t>>2, h = t&3
            int k = t >> 2, h = t & 3;
            float sa = 0.f, sd = 0.f;
            for (int c = 0; c < HID; c++) {
                float w = W1[k * C1 + h * HID + c];
                sa = fmaf(w, as1w[h * HID + c], sa);
                sd = fmaf(w, ad1w[h * HID + c], sd);
            }
            g_wa1[k * HEADS + h] = sa;
            g_wd1[k * HEADS + h] = sd;
        } else if (t < 128) {            // WA2/WD2: k = t-64
            int k = t - 64;
            float sa = 0.f, sd = 0.f;
            for (int c = 0; c < HID; c++) {
                float w = W2[k * HID + c];
                sa = fmaf(w, as2w[c], sa);
                sd = fmaf(w, ad2w[c], sd);
            }
            g_wa2[k] = sa;
            g_wd2[k] = sd;
        }
    }
    const long long* p64 = (const long long*)ei;
    int is64 = 1;
#pragma unroll
    for (int k = 0; k < 16; k++) {
        long long v = p64[k];
        if (v < 0 || v >= NN) is64 = 0;
    }
    int i = blockIdx.x * blockDim.x + threadIdx.x;
    int stride = gridDim.x * blockDim.x;
    if (is64) {
        for (int j = i; j < ETOT; j += stride) {
            if (j < EE) { g_src[j] = clampN((int)p64[j]); g_dst[j] = clampN((int)p64[EE + j]); }
            else        { g_src[j] = g_dst[j] = j - EE; }
        }
    } else {
        const int* p = (const int*)ei;
        for (int j = i; j < ETOT; j += stride) {
            if (j < EE) { g_src[j] = clampN(p[j]); g_dst[j] = clampN(p[EE + j]); }
            else        { g_src[j] = g_dst[j] = j - EE; }
        }
    }
    for (int j = i; j < NN * HID; j += stride) { g_out1[j] = 0.f; g_out2[j] = 0.f; }
    for (int j = i; j < NN * HEADS; j += stride) g_dn1[j] = 0.f;
    for (int j = i; j < NN; j += stride)         g_dn2[j] = 0.f;
}

// h1 = x @ W1 (16 -> 256, stored fp16 via __half2 packed stores) + attention
// dots via hoisted WA/WD. 16 nodes/block, W1 value reused across 16 accumulators.
#define NB1 16
__global__ void k_gemm1(const float* __restrict__ x, const float* __restrict__ W) {
    int t = threadIdx.x;                // channel 0..255
    int nb = blockIdx.x * NB1;
    __shared__ float xs[NB1][16];
    if (t < NB1 * 16) {
        int n = nb + (t >> 4);
        xs[t >> 4][t & 15] = (n < NN) ? x[n * 16 + (t & 15)] : 0.f;
    }
    __syncthreads();
    float acc[NB1];
#pragma unroll
    for (int j = 0; j < NB1; j++) acc[j] = 0.f;
#pragma unroll
    for (int k = 0; k < 16; k++) {
        float wv = W[k * C1 + t];
#pragma unroll
        for (int j = 0; j < NB1; j++) acc[j] = fmaf(xs[j][k], wv, acc[j]);
    }
    // packed fp16 stores: even lanes write (t, t+1) as one __half2 (STG.32)
#pragma unroll
    for (int j = 0; j < NB1; j++) {
        float other = __shfl_xor_sync(0xffffffffu, acc[j], 1);
        int n = nb + j;
        if (((t & 1) == 0) && n < NN) {
            __half2 hv = __halves2half2(__float2half(acc[j]), __float2half(other));
            *(__half2*)&g_h1h[n * C1 + t] = hv;
        }
    }
    // attention dots from xs via hoisted projections: 64 threads, 16 FMA each
    if (t < NB1 * HEADS) {
        int j = t >> 2, h = t & 3;
        int n = nb + j;
        if (n < NN) {
            float sa = 0.f, sd = 0.f;
#pragma unroll
            for (int k = 0; k < 16; k++) {
                float xv = xs[j][k];
                sa = fmaf(xv, g_wa1[k * HEADS + h], sa);
                sd = fmaf(xv, g_wd1[k * HEADS + h], sd);
            }
            g_as1[n * HEADS + h] = sa;
            g_ad1[n * HEADS + h] = sd;
        }
    }
}

// exp(leaky_relu(e)) per edge (logits O(1): no max shift; __expf), store,
// vector-RED denominators.
__global__ void k_exp1() {
    int idx = blockIdx.x * blockDim.x + threadIdx.x;
    if (idx >= ETOT) return;
    int s = g_src[idx], d = g_dst[idx];
    float4 a = *(const float4*)&g_as1[s * 4];
    float4 b = *(const float4*)&g_ad1[d * 4];
    float4 e;
    e.x = __expf(lrelu(a.x + b.x));
    e.y = __expf(lrelu(a.y + b.y));
    e.z = __expf(lrelu(a.z + b.z));
    e.w = __expf(lrelu(a.w + b.w));
    *(float4*)&g_ex1[idx * 4] = e;
    atomicAdd((float4*)&g_dn1[d * 4], e);
}

// Per-node reciprocal fold for layer 1.
__global__ void k_rcp1() {
    int i = blockIdx.x * blockDim.x + threadIdx.x;
    if (i < NN * HEADS) g_dn1[i] = 0.25f / (g_dn1[i] + 1e-16f);
}

// message scatter (layer 1): HALF-warp per edge, fp16 gathers, head-mean fused.
__global__ void k_scat1() {
    int gt = blockIdx.x * blockDim.x + threadIdx.x;
    int e = gt >> 4, l16 = gt & 15;                // 16 lanes per edge
    if (e >= ETOT) return;
    int s = g_src[e], d = g_dst[e];
    float4 ex = *(const float4*)&g_ex1[e * 4];     // broadcast within half-warp
    float4 rc = *(const float4*)&g_dn1[d * 4];     // already 0.25/denom
    float a0 = ex.x * rc.x;
    float a1 = ex.y * rc.y;
    float a2 = ex.z * rc.z;
    float a3 = ex.w * rc.w;
    const __half* hp = &g_h1h[s * C1 + 4 * l16];   // channels 4*l16..+3
    float4 f0 = h4_to_f4(*(const uint2*)(hp));
    float4 f1 = h4_to_f4(*(const uint2*)(hp + 64));
    float4 f2 = h4_to_f4(*(const uint2*)(hp + 128));
    float4 f3 = h4_to_f4(*(const uint2*)(hp + 192));
    float4 v;
    v.x = a0 * f0.x + a1 * f1.x + a2 * f2.x + a3 * f3.x;
    v.y = a0 * f0.y + a1 * f1.y + a2 * f2.y + a3 * f3.y;
    v.z = a0 * f0.z + a1 * f1.z + a2 * f2.z + a3 * f3.z;
    v.w = a0 * f0.w + a1 * f1.w + a2 * f2.w + a3 * f3.w;
    atomicAdd((float4*)&g_out1[d * HID + 4 * l16], v);
}

// h2 = elu(out1 + b1) @ W2 (64 -> 64, stored fp16 packed) + attention dots via
// WA2/WD2 (fp32, from smem — unaffected by fp16 h2). 16 nodes/block.
#define NB2 16
__global__ void k_gemm2(const float* __restrict__ W, const float* __restrict__ b1) {
    int t = threadIdx.x;
    int sub = t >> 6, tc = t & 63;      // 4 subs x 64 channels
    int nb = blockIdx.x * NB2;
    __shared__ float xs[NB2][65];       // padded
    for (int j = t; j < NB2 * 64; j += 256) {
        int n = nb + (j >> 6);
        xs[j >> 6][j & 63] = (n < NN) ? elu_f(g_out1[n * 64 + (j & 63)] + b1[j & 63]) : 0.f;
    }
    __syncthreads();
    float acc[4] = {0.f, 0.f, 0.f, 0.f};
#pragma unroll 8
    for (int k = 0; k < 64; k++) {
        float wv = W[k * 64 + tc];
#pragma unroll
        for (int j = 0; j < 4; j++) acc[j] = fmaf(xs[sub * 4 + j][k], wv, acc[j]);
    }
    // packed fp16 stores (even lanes write __half2)
#pragma unroll
    for (int j = 0; j < 4; j++) {
        float other = __shfl_xor_sync(0xffffffffu, acc[j], 1);
        int n = nb + sub * 4 + j;
        if (((t & 1) == 0) && n < NN) {
            __half2 hv = __halves2half2(__float2half(acc[j]), __float2half(other));
            *(__half2*)&g_h2h[n * 64 + tc] = hv;
        }
    }
    // attention dots: 16 threads, 64 FMA x2 each, from fp32 smem + WA2/WD2
    if (t < NB2) {
        int n = nb + t;
        if (n < NN) {
            float sa = 0.f, sd = 0.f;
#pragma unroll 8
            for (int k = 0; k < 64; k++) {
                float xv = xs[t][k];
                sa = fmaf(xv, g_wa2[k], sa);
                sd = fmaf(xv, g_wd2[k], sd);
            }
            g_as2[n] = sa;
            g_ad2[n] = sd;
        }
    }
}

// FUSED layer-2 edge pass (deferred normalization): fp16 gathers (128B/edge),
// scatter unnormalized ex*h into out2 and ex into dn2.
__global__ void k_scat2f() {
    int gt = blockIdx.x * blockDim.x + threadIdx.x;
    int e = gt >> 4, l16 = gt & 15;
    if (e >= ETOT) return;
    int s = g_src[e], d = g_dst[e];
    float ex = __expf(lrelu(g_as2[s] + g_ad2[d]));
    float4 h = h4_to_f4(*(const uint2*)&g_h2h[s * 64 + 4 * l16]);
    float4 v;
    v.x = ex * h.x; v.y = ex * h.y; v.z = ex * h.z; v.w = ex * h.w;
    atomicAdd((float4*)&g_out2[d * 64 + 4 * l16], v);
    if (l16 == 0) atomicAdd(&g_dn2[d], ex);
}

// Final: normalize by per-node denominator, add bias, ELU.
__global__ void k_fin2(const float* __restrict__ b2, float* __restrict__ out) {
    int i = blockIdx.x * blockDim.x + threadIdx.x;
    if (i >= NN * HID) return;
    float inv = 1.0f / (g_dn2[i >> 6] + 1e-16f);
    out[i] = elu_f(g_out2[i] * inv + b2[i & 63]);
}

// ---------------- launch ----------------
extern "C" void kernel_launch(void* const* d_in, const int* in_sizes, int n_in,
                              void* d_out, int out_size) {
    const float* x    = (const float*)d_in[0];
    const void*  ei   = d_in[1];               // int32 or int64, detected on device
    const float* W1   = (const float*)d_in[2];
    const float* as1w = (const float*)d_in[3];
    const float* ad1w = (const float*)d_in[4];
    const float* b1   = (const float*)d_in[5];
    const float* W2   = (const float*)d_in[6];
    const float* as2w = (const float*)d_in[7];
    const float* ad2w = (const float*)d_in[8];
    const float* b2   = (const float*)d_in[9];
    float*       out  = (float*)d_out;

    const int TB = 256;
    int edge_blocks  = (ETOT + TB - 1) / TB;                 // thread per edge
    int hwarp_blocks = (ETOT * 16 + TB - 1) / TB;            // half-warp per edge
    int node_blocks  = (NN * HID + TB - 1) / TB;

    k_prep<<<2048, TB>>>(ei, W1, as1w, ad1w, W2, as2w, ad2w);
    k_gemm1<<<(NN + NB1 - 1) / NB1, TB>>>(x, W1);
    k_exp1<<<edge_blocks, TB>>>();
    k_rcp1<<<(NN * HEADS + TB - 1) / TB, TB>>>();
    k_scat1<<<hwarp_blocks, TB>>>();
    k_gemm2<<<(NN + NB2 - 1) / NB2, TB>>>(W2, b1);
    k_scat2f<<<hwarp_blocks, TB>>>();
    k_fin2<<<node_blocks, TB>>>(b2, out);
}